// round 11
// baseline (speedup 1.0000x reference)
#include <cuda_runtime.h>
#include <cuda_bf16.h>
#include <cuda_fp16.h>
#include <cstdint>

#define N_SRC   50000
#define N_DST   50000
#define N_EDGES 800000
#define D       128

// ---------------- device-global scratch (allocation-free) ----------------
__device__ __align__(16) __half g_nsrc_h[N_SRC * D];  // fp16 relu(Q h_src + b)
__device__ __align__(16) float  g_nacc[N_DST * D];    // normalized aggregate
__device__ __align__(16) float  g_part[N_DST * D];    // h_dst @ W2^T partial
__device__ int   g_cnt[N_DST];
__device__ int   g_startv[N_DST];
__device__ int   g_cursor[N_DST];
__device__ int   g_total;
__device__ __align__(8) uint2 g_edge[N_EDGES];        // packed (src, weight)
// Pre-packed weights: bf16 hi/lo pairs, [j][KDIM/2] u32
__device__ __align__(16) uint32_t g_Qhi[128 * 64],  g_Qlo[128 * 64];
__device__ __align__(16) uint32_t g_Whi[128 * 128], g_Wlo[128 * 128];

// ---------------------------------------------------------------------------
// bf16x3 split helpers
// ---------------------------------------------------------------------------
__device__ __forceinline__ void pack2(float x, float y,
                                      uint32_t& hi, uint32_t& lo) {
    __nv_bfloat162 h = __floats2bfloat162_rn(x, y);
    uint32_t hu = reinterpret_cast<uint32_t&>(h);
    float fx = __uint_as_float(hu << 16);
    float fy = __uint_as_float(hu & 0xFFFF0000u);
    __nv_bfloat162 l = __floats2bfloat162_rn(x - fx, y - fy);
    hi = hu;
    lo = reinterpret_cast<uint32_t&>(l);
}

__device__ __forceinline__ void mma_bf16(float* d, const uint32_t* a,
                                         const uint32_t* b) {
    asm volatile(
        "mma.sync.aligned.m16n8k16.row.col.f32.bf16.bf16.f32 "
        "{%0,%1,%2,%3}, {%4,%5,%6,%7}, {%8,%9}, {%0,%1,%2,%3};"
        : "+f"(d[0]), "+f"(d[1]), "+f"(d[2]), "+f"(d[3])
        : "r"(a[0]), "r"(a[1]), "r"(a[2]), "r"(a[3]),
          "r"(b[0]), "r"(b[1]));
}

// ---------------------------------------------------------------------------
// Fused prep: zero g_cnt + g_total, pre-pack Q_w / W_w.
// ---------------------------------------------------------------------------
__global__ void prep_kernel(const float* __restrict__ Qw,
                            const float* __restrict__ Ww) {
    const int nq = 128 * 64, nw = 128 * 128;
    int i = blockIdx.x * blockDim.x + threadIdx.x;
    if (i < N_DST) g_cnt[i] = 0;
    if (i == 0)    g_total = 0;
    if (i < nq) {
        float2 v = *(const float2*)(Qw + i * 2);
        pack2(v.x, v.y, g_Qhi[i], g_Qlo[i]);
    } else if (i < nq + nw) {
        int j = i - nq;
        float2 v = *(const float2*)(Ww + j * 2);
        pack2(v.x, v.y, g_Whi[j], g_Wlo[j]);
    }
}

// ---------------------------------------------------------------------------
// CSR build: histogram -> atomic segment alloc -> scatter (packed 8B stores)
// ---------------------------------------------------------------------------
__global__ void hist_kernel(const int* __restrict__ edst) {
    int e = blockIdx.x * blockDim.x + threadIdx.x;
    if (e < N_EDGES) atomicAdd(&g_cnt[edst[e]], 1);
}

__global__ void alloc_kernel() {
    const int i    = blockIdx.x * blockDim.x + threadIdx.x;
    const int lane = threadIdx.x & 31;
    int c = (i < N_DST) ? g_cnt[i] : 0;
    int pfx = c;
#pragma unroll
    for (int o = 1; o < 32; o <<= 1) {
        int v = __shfl_up_sync(0xffffffffu, pfx, o);
        if (lane >= o) pfx += v;
    }
    int wtot = __shfl_sync(0xffffffffu, pfx, 31);
    int wbase = 0;
    if (lane == 31) wbase = atomicAdd(&g_total, wtot);
    wbase = __shfl_sync(0xffffffffu, wbase, 31);
    if (i < N_DST) {
        int base = wbase + pfx - c;
        g_startv[i] = base;
        g_cursor[i] = base;
    }
}

__global__ void scatter_kernel(const int* __restrict__ esrc,
                               const int* __restrict__ edst,
                               const float* __restrict__ weights) {
    int e = blockIdx.x * blockDim.x + threadIdx.x;
    if (e >= N_EDGES) return;
    int d   = edst[e];
    int pos = atomicAdd(&g_cursor[d], 1);
    g_edge[pos] = make_uint2((uint32_t)esrc[e], __float_as_uint(weights[e]));
}

// ---------------------------------------------------------------------------
// Aggregation: one warp per dst, fp16 gather (x4 unroll), fp32 accumulate,
// single normalized fp32 write (identical to R9).
// ---------------------------------------------------------------------------
__global__ void aggregate_csr_kernel() {
    const int warp = (blockIdx.x * blockDim.x + threadIdx.x) >> 5;
    const int lane = threadIdx.x & 31;
    if (warp >= N_DST) return;

    const int beg = g_startv[warp];
    const int n   = g_cnt[warp];

    float4 acc = make_float4(0.f, 0.f, 0.f, 0.f);
    float  wsum = 0.f;

#define ACC_H2(raw, ww) {                                                   \
        float2 p0 = __half22float2(*reinterpret_cast<__half2*>(&(raw).x)); \
        float2 p1 = __half22float2(*reinterpret_cast<__half2*>(&(raw).y)); \
        acc.x = fmaf(p0.x, (ww), acc.x);                                   \
        acc.y = fmaf(p0.y, (ww), acc.y);                                   \
        acc.z = fmaf(p1.x, (ww), acc.z);                                   \
        acc.w = fmaf(p1.y, (ww), acc.w); }

    int i = 0;
    for (; i + 4 <= n; i += 4) {
        uint2 e0 = g_edge[beg + i],     e1 = g_edge[beg + i + 1];
        uint2 e2 = g_edge[beg + i + 2], e3 = g_edge[beg + i + 3];
        uint2 r0 = *(const uint2*)(g_nsrc_h + (size_t)e0.x * D + lane * 4);
        uint2 r1 = *(const uint2*)(g_nsrc_h + (size_t)e1.x * D + lane * 4);
        uint2 r2 = *(const uint2*)(g_nsrc_h + (size_t)e2.x * D + lane * 4);
        uint2 r3 = *(const uint2*)(g_nsrc_h + (size_t)e3.x * D + lane * 4);
        float w0 = __uint_as_float(e0.y), w1 = __uint_as_float(e1.y);
        float w2 = __uint_as_float(e2.y), w3 = __uint_as_float(e3.y);
        ACC_H2(r0, w0); ACC_H2(r1, w1); ACC_H2(r2, w2); ACC_H2(r3, w3);
        wsum += (w0 + w1) + (w2 + w3);
    }
    for (; i < n; ++i) {
        uint2 e = g_edge[beg + i];
        float w = __uint_as_float(e.y);
        uint2 r = *(const uint2*)(g_nsrc_h + (size_t)e.x * D + lane * 4);
        ACC_H2(r, w);
        wsum += w;
    }
#undef ACC_H2

    const float inv = 1.0f / fmaxf(wsum, 1.0f);
    float4 o = make_float4(acc.x * inv, acc.y * inv, acc.z * inv, acc.w * inv);
    *(float4*)(g_nacc + (size_t)warp * D + lane * 4) = o;
}

// ---------------------------------------------------------------------------
// Tensor-core GEMM (bf16x3), KDIM = 128 for all modes:
//   MODE 0: A = h_src,  B = Q_w,          OUT = g_nsrc_h (fp16, +bias, relu)
//   MODE 2: A = h_dst,  B = W_w[:,128:],  OUT = g_part  (fp32, raw)
//   MODE 3: A = g_nacc, B = W_w[:,:128],  OUT = d_out   (fp32, +part+bias, relu)
// ---------------------------------------------------------------------------
template <int MODE>
__global__ void __launch_bounds__(256, 2)
gemm_bf16x3(const float* __restrict__ A0,
            const float* __restrict__ bias,
            float* __restrict__ out,
            int nrows)
{
    constexpr int P    = 20;                       // SMEM u32 pitch
    constexpr int BP   = (MODE == 0) ? 64 : 128;   // u32 per B row
    constexpr int BOFS = (MODE == 2) ? 64 : 0;     // W2 column offset (u32)
    const uint32_t* __restrict__ Bhi = (MODE == 0) ? g_Qhi : g_Whi;
    const uint32_t* __restrict__ Blo = (MODE == 0) ? g_Qlo : g_Wlo;
    const float*    __restrict__ Ap  = (MODE == 3) ? (const float*)g_nacc : A0;

    __shared__ uint32_t As_hi[128 * P];
    __shared__ uint32_t As_lo[128 * P];
    __shared__ uint32_t Bs_hi[128 * P];
    __shared__ uint32_t Bs_lo[128 * P];

    const int tid    = threadIdx.x;
    const int i0     = blockIdx.x * 128;
    const int lane   = tid & 31;
    const int wid    = tid >> 5;
    const int warp_m = wid & 3;
    const int warp_n = wid >> 2;
    const int qr     = lane >> 2;
    const int qc     = lane & 3;

    float acc[2][8][4];
#pragma unroll
    for (int mt = 0; mt < 2; ++mt)
#pragma unroll
        for (int nt = 0; nt < 8; ++nt)
#pragma unroll
            for (int r = 0; r < 4; ++r) acc[mt][nt][r] = 0.f;

    const int  lrow = tid >> 1;
    const int  lkq  = (tid & 1) * 16;
    const int  gi   = i0 + lrow;
    const bool ok   = (gi < nrows);

    for (int kc = 0; kc < 128; kc += 32) {
        __syncthreads();

#pragma unroll
        for (int q = 0; q < 4; ++q) {
            const int gk = kc + lkq + q * 4;
            const int k2 = (lkq + q * 4) >> 1;
            float4 av = make_float4(0.f, 0.f, 0.f, 0.f);
            if (ok) av = *(const float4*)(Ap + (size_t)gi * 128 + gk);
            uint32_t h0, l0, h1, l1;
            pack2(av.x, av.y, h0, l0);
            pack2(av.z, av.w, h1, l1);
            *(uint2*)(As_hi + lrow * P + k2) = make_uint2(h0, h1);
            *(uint2*)(As_lo + lrow * P + k2) = make_uint2(l0, l1);
            const int bidx = lrow * BP + BOFS + (gk >> 1);
            *(uint2*)(Bs_hi + lrow * P + k2) = *(const uint2*)(Bhi + bidx);
            *(uint2*)(Bs_lo + lrow * P + k2) = *(const uint2*)(Blo + bidx);
        }
        __syncthreads();

#pragma unroll
        for (int s = 0; s < 2; ++s) {
            const int ks = s * 8;
            uint32_t ahi[2][4], alo[2][4];
#pragma unroll
            for (int mt = 0; mt < 2; ++mt) {
                const int base = (warp_m * 32 + mt * 16 + qr) * P + ks + qc;
                ahi[mt][0] = As_hi[base];
                ahi[mt][1] = As_hi[base + 8 * P];
                ahi[mt][2] = As_hi[base + 4];
                ahi[mt][3] = As_hi[base + 8 * P + 4];
                alo[mt][0] = As_lo[base];
                alo[mt][1] = As_lo[base + 8 * P];
                alo[mt][2] = As_lo[base + 4];
                alo[mt][3] = As_lo[base + 8 * P + 4];
            }
#pragma unroll
            for (int nt = 0; nt < 8; ++nt) {
                const int bb = (warp_n * 64 + nt * 8 + qr) * P + ks + qc;
                uint32_t bh[2] = { Bs_hi[bb], Bs_hi[bb + 4] };
                uint32_t bl[2] = { Bs_lo[bb], Bs_lo[bb + 4] };
#pragma unroll
                for (int mt = 0; mt < 2; ++mt) {
                    mma_bf16(acc[mt][nt], ahi[mt], bh);
                    mma_bf16(acc[mt][nt], alo[mt], bh);
                    mma_bf16(acc[mt][nt], ahi[mt], bl);
                }
            }
        }
    }

    // ---- Epilogue ----
#pragma unroll
    for (int mt = 0; mt < 2; ++mt) {
#pragma unroll
        for (int half = 0; half < 2; ++half) {
            const int row = i0 + warp_m * 32 + mt * 16 + qr + half * 8;
            if (row < nrows) {
#pragma unroll
                for (int nt = 0; nt < 8; ++nt) {
                    const int col = warp_n * 64 + nt * 8 + qc * 2;
                    float vx = acc[mt][nt][half * 2 + 0];
                    float vy = acc[mt][nt][half * 2 + 1];
                    if (MODE == 0) {
                        vx = fmaxf(vx + bias[col],     0.f);
                        vy = fmaxf(vy + bias[col + 1], 0.f);
                        *(__half2*)(g_nsrc_h + (size_t)row * 128 + col) =
                            __floats2half2_rn(vx, vy);
                    } else if (MODE == 2) {
                        *(float2*)(g_part + (size_t)row * 128 + col) =
                            make_float2(vx, vy);
                    } else {
                        float2 pp = *(const float2*)(g_part + (size_t)row * 128 + col);
                        vx = fmaxf(vx + pp.x + bias[col],     0.f);
                        vy = fmaxf(vy + pp.y + bias[col + 1], 0.f);
                        *(float2*)(out + (size_t)row * 128 + col) =
                            make_float2(vx, vy);
                    }
                }
            }
        }
    }
}

// ---------------------------------------------------------------------------
// Launch graph:
//   main: prep -> gemm0 ----------------------> agg -> gemm1a
//   s2:        \-> hist -> alloc -> scatter -/joinA        /
//   s3:        \-> gemm1b (h_dst @ W2^T) -----------joinB-/
// ---------------------------------------------------------------------------
extern "C" void kernel_launch(void* const* d_in, const int* in_sizes, int n_in,
                              void* d_out, int out_size)
{
    const float* h_src   = (const float*)d_in[0];
    const float* h_dst   = (const float*)d_in[1];
    const float* weights = (const float*)d_in[2];
    const int*   esrc    = (const int*)d_in[3];
    const int*   edst    = (const int*)d_in[4];
    const float* Q_w     = (const float*)d_in[5];
    const float* Q_b     = (const float*)d_in[6];
    const float* W_w     = (const float*)d_in[7];
    const float* W_b     = (const float*)d_in[8];
    float*       out     = (float*)d_out;

    static cudaStream_t s2 = nullptr, s3 = nullptr;
    static cudaEvent_t  evFork = nullptr, evJoinA = nullptr, evJoinB = nullptr;
    if (!s2) {
        cudaStreamCreateWithFlags(&s2, cudaStreamNonBlocking);
        cudaStreamCreateWithFlags(&s3, cudaStreamNonBlocking);
        cudaEventCreateWithFlags(&evFork,  cudaEventDisableTiming);
        cudaEventCreateWithFlags(&evJoinA, cudaEventDisableTiming);
        cudaEventCreateWithFlags(&evJoinB, cudaEventDisableTiming);
    }

    prep_kernel<<<(N_DST + 255) / 256, 256>>>(Q_w, W_w);

    cudaEventRecord(evFork, 0);
    cudaStreamWaitEvent(s2, evFork, 0);
    cudaStreamWaitEvent(s3, evFork, 0);

    // s2: CSR build
    hist_kernel<<<(N_EDGES + 255) / 256, 256, 0, s2>>>(edst);
    alloc_kernel<<<(N_DST + 255) / 256, 256, 0, s2>>>();
    scatter_kernel<<<(N_EDGES + 255) / 256, 256, 0, s2>>>(esrc, edst, weights);
    cudaEventRecord(evJoinA, s2);

    // s3: gemm1b — h_dst @ W2^T partial (independent of CSR/gemm0/aggregate)
    gemm_bf16x3<2><<<(N_DST + 127) / 128, 256, 0, s3>>>(h_dst, nullptr, nullptr, N_DST);
    cudaEventRecord(evJoinB, s3);

    // main: GEMM0 (overlaps s2 + s3)
    gemm_bf16x3<0><<<(N_SRC + 127) / 128, 256>>>(h_src, Q_b, nullptr, N_SRC);

    cudaStreamWaitEvent(0, evJoinA, 0);
    aggregate_csr_kernel<<<(N_DST * 32 + 255) / 256, 256>>>();

    cudaStreamWaitEvent(0, evJoinB, 0);
    gemm_bf16x3<3><<<(N_DST + 127) / 128, 256>>>(nullptr, W_b, out, N_DST);
}

// round 12
// speedup vs baseline: 1.3106x; 1.3106x over previous
#include <cuda_runtime.h>
#include <cuda_bf16.h>
#include <cuda_fp16.h>
#include <cstdint>

#define N_SRC   50000
#define N_DST   50000
#define N_EDGES 800000
#define D       128

// ---------------- device-global scratch (allocation-free) ----------------
__device__ __align__(16) __half g_nsrc_h[N_SRC * D];     // fp16 relu(Q h_src + b)
__device__ __align__(16) uint32_t g_nacc_h[N_DST * 64];  // fp16x2 normalized aggregate
__device__ __align__(16) uint32_t g_hdst_h[N_DST * 64];  // fp16x2 h_dst
__device__ int   g_cnt[N_DST];
__device__ int   g_startv[N_DST];
__device__ int   g_cursor[N_DST];
__device__ int   g_total;
__device__ __align__(8) uint2 g_edge[N_EDGES];           // packed (src, weight)
// Q_w: bf16 hi/lo (for bf16x3 gemm0). W_w: single fp16 (for fp16 gemm1).
__device__ __align__(16) uint32_t g_Qhi[128 * 64], g_Qlo[128 * 64];
__device__ __align__(16) uint32_t g_Wh[128 * 128];

// ---------------------------------------------------------------------------
__device__ __forceinline__ void pack2(float x, float y,
                                      uint32_t& hi, uint32_t& lo) {
    __nv_bfloat162 h = __floats2bfloat162_rn(x, y);
    uint32_t hu = reinterpret_cast<uint32_t&>(h);
    float fx = __uint_as_float(hu << 16);
    float fy = __uint_as_float(hu & 0xFFFF0000u);
    __nv_bfloat162 l = __floats2bfloat162_rn(x - fx, y - fy);
    hi = hu;
    lo = reinterpret_cast<uint32_t&>(l);
}

__device__ __forceinline__ void mma_bf16(float* d, const uint32_t* a,
                                         const uint32_t* b) {
    asm volatile(
        "mma.sync.aligned.m16n8k16.row.col.f32.bf16.bf16.f32 "
        "{%0,%1,%2,%3}, {%4,%5,%6,%7}, {%8,%9}, {%0,%1,%2,%3};"
        : "+f"(d[0]), "+f"(d[1]), "+f"(d[2]), "+f"(d[3])
        : "r"(a[0]), "r"(a[1]), "r"(a[2]), "r"(a[3]),
          "r"(b[0]), "r"(b[1]));
}

__device__ __forceinline__ void mma_f16(float* d, const uint32_t* a,
                                        const uint32_t* b) {
    asm volatile(
        "mma.sync.aligned.m16n8k16.row.col.f32.f16.f16.f32 "
        "{%0,%1,%2,%3}, {%4,%5,%6,%7}, {%8,%9}, {%0,%1,%2,%3};"
        : "+f"(d[0]), "+f"(d[1]), "+f"(d[2]), "+f"(d[3])
        : "r"(a[0]), "r"(a[1]), "r"(a[2]), "r"(a[3]),
          "r"(b[0]), "r"(b[1]));
}

// ---------------------------------------------------------------------------
// Prep: zero g_cnt + g_total, pack Q_w (bf16 hi/lo) and W_w (fp16).
// ---------------------------------------------------------------------------
__global__ void prep_kernel(const float* __restrict__ Qw,
                            const float* __restrict__ Ww) {
    const int nq = 128 * 64, nw = 128 * 128;
    int i = blockIdx.x * blockDim.x + threadIdx.x;
    if (i < N_DST) g_cnt[i] = 0;
    if (i == 0)    g_total = 0;
    if (i < nq) {
        float2 v = *(const float2*)(Qw + i * 2);
        pack2(v.x, v.y, g_Qhi[i], g_Qlo[i]);
    } else if (i < nq + nw) {
        int j = i - nq;
        float2 v = *(const float2*)(Ww + j * 2);
        __half2 h = __floats2half2_rn(v.x, v.y);
        g_Wh[j] = reinterpret_cast<uint32_t&>(h);
    }
}

// Pack h_dst fp32 -> fp16x2 (side stream; small bandwidth kernel).
__global__ void prepack_hdst_kernel(const float* __restrict__ hdst) {
    int i = blockIdx.x * blockDim.x + threadIdx.x;   // u32 index
    if (i >= N_DST * 64) return;
    float2 v = *(const float2*)(hdst + (size_t)i * 2);
    __half2 h = __floats2half2_rn(v.x, v.y);
    g_hdst_h[i] = reinterpret_cast<uint32_t&>(h);
}

// ---------------------------------------------------------------------------
// CSR build: histogram -> atomic segment alloc -> scatter
// ---------------------------------------------------------------------------
__global__ void hist_kernel(const int* __restrict__ edst) {
    int e = blockIdx.x * blockDim.x + threadIdx.x;
    if (e < N_EDGES) atomicAdd(&g_cnt[edst[e]], 1);
}

__global__ void alloc_kernel() {
    const int i    = blockIdx.x * blockDim.x + threadIdx.x;
    const int lane = threadIdx.x & 31;
    int c = (i < N_DST) ? g_cnt[i] : 0;
    int pfx = c;
#pragma unroll
    for (int o = 1; o < 32; o <<= 1) {
        int v = __shfl_up_sync(0xffffffffu, pfx, o);
        if (lane >= o) pfx += v;
    }
    int wtot = __shfl_sync(0xffffffffu, pfx, 31);
    int wbase = 0;
    if (lane == 31) wbase = atomicAdd(&g_total, wtot);
    wbase = __shfl_sync(0xffffffffu, wbase, 31);
    if (i < N_DST) {
        int base = wbase + pfx - c;
        g_startv[i] = base;
        g_cursor[i] = base;
    }
}

__global__ void scatter_kernel(const int* __restrict__ esrc,
                               const int* __restrict__ edst,
                               const float* __restrict__ weights) {
    int e = blockIdx.x * blockDim.x + threadIdx.x;
    if (e >= N_EDGES) return;
    int d   = edst[e];
    int pos = atomicAdd(&g_cursor[d], 1);
    g_edge[pos] = make_uint2((uint32_t)esrc[e], __float_as_uint(weights[e]));
}

// ---------------------------------------------------------------------------
// Aggregation: one warp per dst, fp16 gather (x4 unroll), fp32 accumulate,
// normalized fp16 output (direct gemm1 operand).
// ---------------------------------------------------------------------------
__global__ void aggregate_csr_kernel() {
    const int warp = (blockIdx.x * blockDim.x + threadIdx.x) >> 5;
    const int lane = threadIdx.x & 31;
    if (warp >= N_DST) return;

    const int beg = g_startv[warp];
    const int n   = g_cnt[warp];

    float4 acc = make_float4(0.f, 0.f, 0.f, 0.f);
    float  wsum = 0.f;

#define ACC_H2(raw, ww) {                                                   \
        float2 p0 = __half22float2(*reinterpret_cast<__half2*>(&(raw).x)); \
        float2 p1 = __half22float2(*reinterpret_cast<__half2*>(&(raw).y)); \
        acc.x = fmaf(p0.x, (ww), acc.x);                                   \
        acc.y = fmaf(p0.y, (ww), acc.y);                                   \
        acc.z = fmaf(p1.x, (ww), acc.z);                                   \
        acc.w = fmaf(p1.y, (ww), acc.w); }

    int i = 0;
    for (; i + 4 <= n; i += 4) {
        uint2 e0 = g_edge[beg + i],     e1 = g_edge[beg + i + 1];
        uint2 e2 = g_edge[beg + i + 2], e3 = g_edge[beg + i + 3];
        uint2 r0 = *(const uint2*)(g_nsrc_h + (size_t)e0.x * D + lane * 4);
        uint2 r1 = *(const uint2*)(g_nsrc_h + (size_t)e1.x * D + lane * 4);
        uint2 r2 = *(const uint2*)(g_nsrc_h + (size_t)e2.x * D + lane * 4);
        uint2 r3 = *(const uint2*)(g_nsrc_h + (size_t)e3.x * D + lane * 4);
        float w0 = __uint_as_float(e0.y), w1 = __uint_as_float(e1.y);
        float w2 = __uint_as_float(e2.y), w3 = __uint_as_float(e3.y);
        ACC_H2(r0, w0); ACC_H2(r1, w1); ACC_H2(r2, w2); ACC_H2(r3, w3);
        wsum += (w0 + w1) + (w2 + w3);
    }
    for (; i < n; ++i) {
        uint2 e = g_edge[beg + i];
        float w = __uint_as_float(e.y);
        uint2 r = *(const uint2*)(g_nsrc_h + (size_t)e.x * D + lane * 4);
        ACC_H2(r, w);
        wsum += w;
    }
#undef ACC_H2

    const float inv = 1.0f / fmaxf(wsum, 1.0f);
    __half2 h0 = __floats2half2_rn(acc.x * inv, acc.y * inv);
    __half2 h1 = __floats2half2_rn(acc.z * inv, acc.w * inv);
    *(uint2*)(g_nacc_h + (size_t)warp * 64 + lane * 2) =
        make_uint2(reinterpret_cast<uint32_t&>(h0),
                   reinterpret_cast<uint32_t&>(h1));
}

// ---------------------------------------------------------------------------
// GEMM0 (bf16x3): g_nsrc_h = relu(h_src @ Q_w^T + Q_b), KDIM=128.
// (Unchanged from R9 MODE 0.)
// ---------------------------------------------------------------------------
__global__ void __launch_bounds__(256, 2)
gemm0_bf16x3(const float* __restrict__ A0,
             const float* __restrict__ bias,
             int nrows)
{
    constexpr int P = 20;
    __shared__ uint32_t As_hi[128 * P];
    __shared__ uint32_t As_lo[128 * P];
    __shared__ uint32_t Bs_hi[128 * P];
    __shared__ uint32_t Bs_lo[128 * P];

    const int tid    = threadIdx.x;
    const int i0     = blockIdx.x * 128;
    const int lane   = tid & 31;
    const int wid    = tid >> 5;
    const int warp_m = wid & 3;
    const int warp_n = wid >> 2;
    const int qr     = lane >> 2;
    const int qc     = lane & 3;

    float acc[2][8][4];
#pragma unroll
    for (int mt = 0; mt < 2; ++mt)
#pragma unroll
        for (int nt = 0; nt < 8; ++nt)
#pragma unroll
            for (int r = 0; r < 4; ++r) acc[mt][nt][r] = 0.f;

    const int  lrow = tid >> 1;
    const int  lkq  = (tid & 1) * 16;
    const int  gi   = i0 + lrow;
    const bool ok   = (gi < nrows);

    for (int kc = 0; kc < 128; kc += 32) {
        __syncthreads();
#pragma unroll
        for (int q = 0; q < 4; ++q) {
            const int gk = kc + lkq + q * 4;
            const int k2 = (lkq + q * 4) >> 1;
            float4 av = make_float4(0.f, 0.f, 0.f, 0.f);
            if (ok) av = *(const float4*)(A0 + (size_t)gi * 128 + gk);
            uint32_t h0, l0, h1, l1;
            pack2(av.x, av.y, h0, l0);
            pack2(av.z, av.w, h1, l1);
            *(uint2*)(As_hi + lrow * P + k2) = make_uint2(h0, h1);
            *(uint2*)(As_lo + lrow * P + k2) = make_uint2(l0, l1);
            const int bidx = lrow * 64 + (gk >> 1);
            *(uint2*)(Bs_hi + lrow * P + k2) = *(const uint2*)(g_Qhi + bidx);
            *(uint2*)(Bs_lo + lrow * P + k2) = *(const uint2*)(g_Qlo + bidx);
        }
        __syncthreads();

#pragma unroll
        for (int s = 0; s < 2; ++s) {
            const int ks = s * 8;
            uint32_t ahi[2][4], alo[2][4];
#pragma unroll
            for (int mt = 0; mt < 2; ++mt) {
                const int base = (warp_m * 32 + mt * 16 + qr) * P + ks + qc;
                ahi[mt][0] = As_hi[base];
                ahi[mt][1] = As_hi[base + 8 * P];
                ahi[mt][2] = As_hi[base + 4];
                ahi[mt][3] = As_hi[base + 8 * P + 4];
                alo[mt][0] = As_lo[base];
                alo[mt][1] = As_lo[base + 8 * P];
                alo[mt][2] = As_lo[base + 4];
                alo[mt][3] = As_lo[base + 8 * P + 4];
            }
#pragma unroll
            for (int nt = 0; nt < 8; ++nt) {
                const int bb = (warp_n * 64 + nt * 8 + qr) * P + ks + qc;
                uint32_t bh[2] = { Bs_hi[bb], Bs_hi[bb + 4] };
                uint32_t bl[2] = { Bs_lo[bb], Bs_lo[bb + 4] };
#pragma unroll
                for (int mt = 0; mt < 2; ++mt) {
                    mma_bf16(acc[mt][nt], ahi[mt], bh);
                    mma_bf16(acc[mt][nt], alo[mt], bh);
                    mma_bf16(acc[mt][nt], ahi[mt], bl);
                }
            }
        }
    }

#pragma unroll
    for (int mt = 0; mt < 2; ++mt)
#pragma unroll
        for (int half = 0; half < 2; ++half) {
            const int row = i0 + warp_m * 32 + mt * 16 + qr + half * 8;
            if (row < nrows) {
#pragma unroll
                for (int nt = 0; nt < 8; ++nt) {
                    const int col = warp_n * 64 + nt * 8 + qc * 2;
                    float vx = fmaxf(acc[mt][nt][half * 2 + 0] + bias[col],     0.f);
                    float vy = fmaxf(acc[mt][nt][half * 2 + 1] + bias[col + 1], 0.f);
                    *(__half2*)(g_nsrc_h + (size_t)row * 128 + col) =
                        __floats2half2_rn(vx, vy);
                }
            }
        }
}

// ---------------------------------------------------------------------------
// GEMM1 (single-pass fp16): out = relu([nacc|hdst] @ W_w^T + W_b), KDIM=256.
// A = fp16 pre-packed (g_nacc_h | g_hdst_h), B = g_Wh. 1 mma per tile pair.
// ---------------------------------------------------------------------------
__global__ void __launch_bounds__(256, 2)
gemm1_f16(const float* __restrict__ bias,
          float* __restrict__ out,
          int nrows)
{
    constexpr int P = 20;
    __shared__ uint32_t As[128 * P];
    __shared__ uint32_t Bs[128 * P];

    const int tid    = threadIdx.x;
    const int i0     = blockIdx.x * 128;
    const int lane   = tid & 31;
    const int wid    = tid >> 5;
    const int warp_m = wid & 3;
    const int warp_n = wid >> 2;
    const int qr     = lane >> 2;
    const int qc     = lane & 3;

    float acc[2][8][4];
#pragma unroll
    for (int mt = 0; mt < 2; ++mt)
#pragma unroll
        for (int nt = 0; nt < 8; ++nt)
#pragma unroll
            for (int r = 0; r < 4; ++r) acc[mt][nt][r] = 0.f;

    const int  lrow = tid >> 1;
    const int  lkq  = (tid & 1) * 16;      // k offset in halves: 0 or 16
    const int  gi   = i0 + lrow;
    const bool ok   = (gi < nrows);

    for (int kc = 0; kc < 256; kc += 32) {
        __syncthreads();
#pragma unroll
        for (int q = 0; q < 2; ++q) {      // 2 x uint4 = 8 u32 per thread
            const int gk = kc + lkq + q * 8;          // halves
            const int k2 = (lkq + q * 8) >> 1;        // u32 col in SMEM row
            uint4 a = make_uint4(0u, 0u, 0u, 0u);
            if (ok) {
                if (gk < 128)
                    a = *(const uint4*)(g_nacc_h + (size_t)gi * 64 + (gk >> 1));
                else
                    a = *(const uint4*)(g_hdst_h + (size_t)gi * 64 + ((gk - 128) >> 1));
            }
            *(uint4*)(As + lrow * P + k2) = a;
            *(uint4*)(Bs + lrow * P + k2) =
                *(const uint4*)(g_Wh + lrow * 128 + (gk >> 1));
        }
        __syncthreads();

#pragma unroll
        for (int s = 0; s < 2; ++s) {
            const int ks = s * 8;
            uint32_t a[2][4];
#pragma unroll
            for (int mt = 0; mt < 2; ++mt) {
                const int base = (warp_m * 32 + mt * 16 + qr) * P + ks + qc;
                a[mt][0] = As[base];
                a[mt][1] = As[base + 8 * P];
                a[mt][2] = As[base + 4];
                a[mt][3] = As[base + 8 * P + 4];
            }
#pragma unroll
            for (int nt = 0; nt < 8; ++nt) {
                const int bb = (warp_n * 64 + nt * 8 + qr) * P + ks + qc;
                uint32_t b[2] = { Bs[bb], Bs[bb + 4] };
#pragma unroll
                for (int mt = 0; mt < 2; ++mt)
                    mma_f16(acc[mt][nt], a[mt], b);
            }
        }
    }

#pragma unroll
    for (int mt = 0; mt < 2; ++mt)
#pragma unroll
        for (int half = 0; half < 2; ++half) {
            const int row = i0 + warp_m * 32 + mt * 16 + qr + half * 8;
            if (row < nrows) {
#pragma unroll
                for (int nt = 0; nt < 8; ++nt) {
                    const int col = warp_n * 64 + nt * 8 + qc * 2;
                    float vx = fmaxf(acc[mt][nt][half * 2 + 0] + bias[col],     0.f);
                    float vy = fmaxf(acc[mt][nt][half * 2 + 1] + bias[col + 1], 0.f);
                    *(float2*)(out + (size_t)row * 128 + col) = make_float2(vx, vy);
                }
            }
        }
}

// ---------------------------------------------------------------------------
// Launch graph (R9 structure):
//   main: prep -> gemm0 -------------------------------> agg -> gemm1
//   s2:        \-> hdst_pack -> hist -> alloc -> scatter -/join
// ---------------------------------------------------------------------------
extern "C" void kernel_launch(void* const* d_in, const int* in_sizes, int n_in,
                              void* d_out, int out_size)
{
    const float* h_src   = (const float*)d_in[0];
    const float* h_dst   = (const float*)d_in[1];
    const float* weights = (const float*)d_in[2];
    const int*   esrc    = (const int*)d_in[3];
    const int*   edst    = (const int*)d_in[4];
    const float* Q_w     = (const float*)d_in[5];
    const float* Q_b     = (const float*)d_in[6];
    const float* W_w     = (const float*)d_in[7];
    const float* W_b     = (const float*)d_in[8];
    float*       out     = (float*)d_out;

    static cudaStream_t s2 = nullptr;
    static cudaEvent_t  evFork = nullptr, evJoin = nullptr;
    if (!s2) {
        cudaStreamCreateWithFlags(&s2, cudaStreamNonBlocking);
        cudaEventCreateWithFlags(&evFork, cudaEventDisableTiming);
        cudaEventCreateWithFlags(&evJoin, cudaEventDisableTiming);
    }

    prep_kernel<<<(N_DST + 255) / 256, 256>>>(Q_w, W_w);

    cudaEventRecord(evFork, 0);
    cudaStreamWaitEvent(s2, evFork, 0);

    // s2: h_dst fp16 pack + CSR build (all small kernels — overlap gemm0)
    prepack_hdst_kernel<<<(N_DST * 64 + 255) / 256, 256, 0, s2>>>(h_dst);
    hist_kernel<<<(N_EDGES + 255) / 256, 256, 0, s2>>>(edst);
    alloc_kernel<<<(N_DST + 255) / 256, 256, 0, s2>>>();
    scatter_kernel<<<(N_EDGES + 255) / 256, 256, 0, s2>>>(esrc, edst, weights);
    cudaEventRecord(evJoin, s2);

    // main: GEMM0 (overlaps s2)
    gemm0_bf16x3<<<(N_SRC + 127) / 128, 256>>>(h_src, Q_b, N_SRC);

    cudaStreamWaitEvent(0, evJoin, 0);
    aggregate_csr_kernel<<<(N_DST * 32 + 255) / 256, 256>>>();
    gemm1_f16<<<(N_DST + 127) / 128, 256>>>(W_b, out, N_DST);
}

// round 13
// speedup vs baseline: 1.3928x; 1.0628x over previous
#include <cuda_runtime.h>
#include <cuda_fp16.h>
#include <cstdint>

#define N_SRC   50000
#define N_DST   50000
#define N_EDGES 800000
#define D       128

// ---------------- device-global scratch (allocation-free) ----------------
__device__ __align__(16) __half g_nsrc_h[N_SRC * D];     // fp16 relu(Q h_src + b)
__device__ __align__(16) uint32_t g_nacc_h[N_DST * 64];  // fp16x2 normalized aggregate
__device__ __align__(16) uint32_t g_hdst_h[N_DST * 64];  // fp16x2 h_dst
__device__ int   g_cnt[N_DST];
__device__ int   g_startv[N_DST];
__device__ int   g_cursor[N_DST];
__device__ int   g_total;
__device__ __align__(8) uint2 g_edge[N_EDGES];           // packed (src, weight)
// fp16-packed weights (u32 = fp16x2): Q_w [128][64], W_w [128][128]
__device__ __align__(16) uint32_t g_Qh[128 * 64];
__device__ __align__(16) uint32_t g_Wh[128 * 128];

// ---------------------------------------------------------------------------
__device__ __forceinline__ void mma_f16(float* d, const uint32_t* a,
                                        const uint32_t* b) {
    asm volatile(
        "mma.sync.aligned.m16n8k16.row.col.f32.f16.f16.f32 "
        "{%0,%1,%2,%3}, {%4,%5,%6,%7}, {%8,%9}, {%0,%1,%2,%3};"
        : "+f"(d[0]), "+f"(d[1]), "+f"(d[2]), "+f"(d[3])
        : "r"(a[0]), "r"(a[1]), "r"(a[2]), "r"(a[3]),
          "r"(b[0]), "r"(b[1]));
}

__device__ __forceinline__ uint32_t f2h2(float x, float y) {
    __half2 h = __floats2half2_rn(x, y);
    return reinterpret_cast<uint32_t&>(h);
}

// ---------------------------------------------------------------------------
// Prep: zero g_cnt + g_total, pack Q_w and W_w to fp16.
// ---------------------------------------------------------------------------
__global__ void prep_kernel(const float* __restrict__ Qw,
                            const float* __restrict__ Ww) {
    const int nq = 128 * 64, nw = 128 * 128;
    int i = blockIdx.x * blockDim.x + threadIdx.x;
    if (i < N_DST) g_cnt[i] = 0;
    if (i == 0)    g_total = 0;
    if (i < nq) {
        float2 v = *(const float2*)(Qw + i * 2);
        g_Qh[i] = f2h2(v.x, v.y);
    } else if (i < nq + nw) {
        int j = i - nq;
        float2 v = *(const float2*)(Ww + j * 2);
        g_Wh[j] = f2h2(v.x, v.y);
    }
}

// Pack h_dst fp32 -> fp16x2 (side stream).
__global__ void prepack_hdst_kernel(const float* __restrict__ hdst) {
    int i = blockIdx.x * blockDim.x + threadIdx.x;
    if (i >= N_DST * 64) return;
    float2 v = *(const float2*)(hdst + (size_t)i * 2);
    g_hdst_h[i] = f2h2(v.x, v.y);
}

// ---------------------------------------------------------------------------
// CSR build: histogram -> atomic segment alloc -> scatter
// ---------------------------------------------------------------------------
__global__ void hist_kernel(const int* __restrict__ edst) {
    int e = blockIdx.x * blockDim.x + threadIdx.x;
    if (e < N_EDGES) atomicAdd(&g_cnt[edst[e]], 1);
}

__global__ void alloc_kernel() {
    const int i    = blockIdx.x * blockDim.x + threadIdx.x;
    const int lane = threadIdx.x & 31;
    int c = (i < N_DST) ? g_cnt[i] : 0;
    int pfx = c;
#pragma unroll
    for (int o = 1; o < 32; o <<= 1) {
        int v = __shfl_up_sync(0xffffffffu, pfx, o);
        if (lane >= o) pfx += v;
    }
    int wtot = __shfl_sync(0xffffffffu, pfx, 31);
    int wbase = 0;
    if (lane == 31) wbase = atomicAdd(&g_total, wtot);
    wbase = __shfl_sync(0xffffffffu, wbase, 31);
    if (i < N_DST) {
        int base = wbase + pfx - c;
        g_startv[i] = base;
        g_cursor[i] = base;
    }
}

__global__ void scatter_kernel(const int* __restrict__ esrc,
                               const int* __restrict__ edst,
                               const float* __restrict__ weights) {
    int e = blockIdx.x * blockDim.x + threadIdx.x;
    if (e >= N_EDGES) return;
    int d   = edst[e];
    int pos = atomicAdd(&g_cursor[d], 1);
    g_edge[pos] = make_uint2((uint32_t)esrc[e], __float_as_uint(weights[e]));
}

// ---------------------------------------------------------------------------
// Aggregation: one warp per dst, fp16 gather (x4 unroll), fp32 accumulate,
// normalized fp16 output (direct gemm1 operand).
// ---------------------------------------------------------------------------
__global__ void aggregate_csr_kernel() {
    const int warp = (blockIdx.x * blockDim.x + threadIdx.x) >> 5;
    const int lane = threadIdx.x & 31;
    if (warp >= N_DST) return;

    const int beg = g_startv[warp];
    const int n   = g_cnt[warp];

    float4 acc = make_float4(0.f, 0.f, 0.f, 0.f);
    float  wsum = 0.f;

#define ACC_H2(raw, ww) {                                                   \
        float2 p0 = __half22float2(*reinterpret_cast<__half2*>(&(raw).x)); \
        float2 p1 = __half22float2(*reinterpret_cast<__half2*>(&(raw).y)); \
        acc.x = fmaf(p0.x, (ww), acc.x);                                   \
        acc.y = fmaf(p0.y, (ww), acc.y);                                   \
        acc.z = fmaf(p1.x, (ww), acc.z);                                   \
        acc.w = fmaf(p1.y, (ww), acc.w); }

    int i = 0;
    for (; i + 4 <= n; i += 4) {
        uint2 e0 = g_edge[beg + i],     e1 = g_edge[beg + i + 1];
        uint2 e2 = g_edge[beg + i + 2], e3 = g_edge[beg + i + 3];
        uint2 r0 = *(const uint2*)(g_nsrc_h + (size_t)e0.x * D + lane * 4);
        uint2 r1 = *(const uint2*)(g_nsrc_h + (size_t)e1.x * D + lane * 4);
        uint2 r2 = *(const uint2*)(g_nsrc_h + (size_t)e2.x * D + lane * 4);
        uint2 r3 = *(const uint2*)(g_nsrc_h + (size_t)e3.x * D + lane * 4);
        float w0 = __uint_as_float(e0.y), w1 = __uint_as_float(e1.y);
        float w2 = __uint_as_float(e2.y), w3 = __uint_as_float(e3.y);
        ACC_H2(r0, w0); ACC_H2(r1, w1); ACC_H2(r2, w2); ACC_H2(r3, w3);
        wsum += (w0 + w1) + (w2 + w3);
    }
    for (; i < n; ++i) {
        uint2 e = g_edge[beg + i];
        float w = __uint_as_float(e.y);
        uint2 r = *(const uint2*)(g_nsrc_h + (size_t)e.x * D + lane * 4);
        ACC_H2(r, w);
        wsum += w;
    }
#undef ACC_H2

    const float inv = 1.0f / fmaxf(wsum, 1.0f);
    *(uint2*)(g_nacc_h + (size_t)warp * 64 + lane * 2) =
        make_uint2(f2h2(acc.x * inv, acc.y * inv),
                   f2h2(acc.z * inv, acc.w * inv));
}

// ---------------------------------------------------------------------------
// Unified fp16 tensor-core GEMM, 128x128 tile, BK=32, 8 warps (4m x 2n):
//   MODE 0: A = h_src fp32 (cvt in loader), B = g_Qh, KDIM=128,
//           OUT = g_nsrc_h (fp16, +bias, relu)
//   MODE 1: A = [g_nacc_h | g_hdst_h] fp16, B = g_Wh, KDIM=256,
//           OUT = d_out (fp32, +bias, relu)
// ---------------------------------------------------------------------------
template <int MODE>
__global__ void __launch_bounds__(256, 2)
gemm_f16(const float* __restrict__ A0,
         const float* __restrict__ bias,
         float* __restrict__ out,
         int nrows)
{
    constexpr int P    = 20;                      // SMEM u32 pitch
    constexpr int KDIM = (MODE == 0) ? 128 : 256;
    constexpr int BP   = (MODE == 0) ? 64 : 128;  // u32 per B row
    const uint32_t* __restrict__ Bp = (MODE == 0) ? g_Qh : g_Wh;

    __shared__ uint32_t As[128 * P];
    __shared__ uint32_t Bs[128 * P];

    const int tid    = threadIdx.x;
    const int i0     = blockIdx.x * 128;
    const int lane   = tid & 31;
    const int wid    = tid >> 5;
    const int warp_m = wid & 3;
    const int warp_n = wid >> 2;
    const int qr     = lane >> 2;
    const int qc     = lane & 3;

    float acc[2][8][4];
#pragma unroll
    for (int mt = 0; mt < 2; ++mt)
#pragma unroll
        for (int nt = 0; nt < 8; ++nt)
#pragma unroll
            for (int r = 0; r < 4; ++r) acc[mt][nt][r] = 0.f;

    const int  lrow = tid >> 1;
    const int  lkq  = (tid & 1) * 16;      // k offset (halves): 0 or 16
    const int  gi   = i0 + lrow;
    const bool ok   = (gi < nrows);

    for (int kc = 0; kc < KDIM; kc += 32) {
        __syncthreads();
#pragma unroll
        for (int q = 0; q < 2; ++q) {      // 2 x uint4 (8 u32) per thread
            const int gk = kc + lkq + q * 8;       // k in halves
            const int k2 = (lkq + q * 8) >> 1;     // u32 col in SMEM row
            uint4 a = make_uint4(0u, 0u, 0u, 0u);
            if (ok) {
                if (MODE == 0) {
                    float4 v0 = *(const float4*)(A0 + (size_t)gi * 128 + gk);
                    float4 v1 = *(const float4*)(A0 + (size_t)gi * 128 + gk + 4);
                    a = make_uint4(f2h2(v0.x, v0.y), f2h2(v0.z, v0.w),
                                   f2h2(v1.x, v1.y), f2h2(v1.z, v1.w));
                } else {
                    if (gk < 128)
                        a = *(const uint4*)(g_nacc_h + (size_t)gi * 64 + (gk >> 1));
                    else
                        a = *(const uint4*)(g_hdst_h + (size_t)gi * 64 + ((gk - 128) >> 1));
                }
            }
            *(uint4*)(As + lrow * P + k2) = a;
            *(uint4*)(Bs + lrow * P + k2) =
                *(const uint4*)(Bp + lrow * BP + (gk >> 1));
        }
        __syncthreads();

#pragma unroll
        for (int s = 0; s < 2; ++s) {
            const int ks = s * 8;
            uint32_t a[2][4];
#pragma unroll
            for (int mt = 0; mt < 2; ++mt) {
                const int base = (warp_m * 32 + mt * 16 + qr) * P + ks + qc;
                a[mt][0] = As[base];
                a[mt][1] = As[base + 8 * P];
                a[mt][2] = As[base + 4];
                a[mt][3] = As[base + 8 * P + 4];
            }
#pragma unroll
            for (int nt = 0; nt < 8; ++nt) {
                const int bb = (warp_n * 64 + nt * 8 + qr) * P + ks + qc;
                uint32_t b[2] = { Bs[bb], Bs[bb + 4] };
#pragma unroll
                for (int mt = 0; mt < 2; ++mt)
                    mma_f16(acc[mt][nt], a[mt], b);
            }
        }
    }

#pragma unroll
    for (int mt = 0; mt < 2; ++mt)
#pragma unroll
        for (int half = 0; half < 2; ++half) {
            const int row = i0 + warp_m * 32 + mt * 16 + qr + half * 8;
            if (row < nrows) {
#pragma unroll
                for (int nt = 0; nt < 8; ++nt) {
                    const int col = warp_n * 64 + nt * 8 + qc * 2;
                    float vx = fmaxf(acc[mt][nt][half * 2 + 0] + bias[col],     0.f);
                    float vy = fmaxf(acc[mt][nt][half * 2 + 1] + bias[col + 1], 0.f);
                    if (MODE == 0) {
                        *(__half2*)(g_nsrc_h + (size_t)row * 128 + col) =
                            __floats2half2_rn(vx, vy);
                    } else {
                        *(float2*)(out + (size_t)row * 128 + col) =
                            make_float2(vx, vy);
                    }
                }
            }
        }
}

// ---------------------------------------------------------------------------
// Launch graph:
//   main: prep -> gemm0 -------------------------------> agg -> gemm1
//   s2:        \-> hdst_pack -> hist -> alloc -> scatter -/join
// ---------------------------------------------------------------------------
extern "C" void kernel_launch(void* const* d_in, const int* in_sizes, int n_in,
                              void* d_out, int out_size)
{
    const float* h_src   = (const float*)d_in[0];
    const float* h_dst   = (const float*)d_in[1];
    const float* weights = (const float*)d_in[2];
    const int*   esrc    = (const int*)d_in[3];
    const int*   edst    = (const int*)d_in[4];
    const float* Q_w     = (const float*)d_in[5];
    const float* Q_b     = (const float*)d_in[6];
    const float* W_w     = (const float*)d_in[7];
    const float* W_b     = (const float*)d_in[8];
    float*       out     = (float*)d_out;

    static cudaStream_t s2 = nullptr;
    static cudaEvent_t  evFork = nullptr, evJoin = nullptr;
    if (!s2) {
        cudaStreamCreateWithFlags(&s2, cudaStreamNonBlocking);
        cudaEventCreateWithFlags(&evFork, cudaEventDisableTiming);
        cudaEventCreateWithFlags(&evJoin, cudaEventDisableTiming);
    }

    prep_kernel<<<(N_DST + 255) / 256, 256>>>(Q_w, W_w);

    cudaEventRecord(evFork, 0);
    cudaStreamWaitEvent(s2, evFork, 0);

    // s2: h_dst fp16 pack + CSR build (small kernels — overlap gemm0)
    prepack_hdst_kernel<<<(N_DST * 64 + 255) / 256, 256, 0, s2>>>(h_dst);
    hist_kernel<<<(N_EDGES + 255) / 256, 256, 0, s2>>>(edst);
    alloc_kernel<<<(N_DST + 255) / 256, 256, 0, s2>>>();
    scatter_kernel<<<(N_EDGES + 255) / 256, 256, 0, s2>>>(esrc, edst, weights);
    cudaEventRecord(evJoin, s2);

    // main: GEMM0 (overlaps s2)
    gemm_f16<0><<<(N_SRC + 127) / 128, 256>>>(h_src, Q_b, nullptr, N_SRC);

    cudaStreamWaitEvent(0, evJoin, 0);
    aggregate_csr_kernel<<<(N_DST * 32 + 255) / 256, 256>>>();
    gemm_f16<1><<<(N_DST + 127) / 128, 256>>>(nullptr, W_b, out, N_DST);
}

// round 14
// speedup vs baseline: 1.4216x; 1.0206x over previous
#include <cuda_runtime.h>
#include <cuda_fp16.h>
#include <cstdint>

#define N_SRC   50000
#define N_DST   50000
#define N_EDGES 800000
#define D       128
#define SPLIT   25088          // 196 * 128 — gemm tile aligned row split

// ---------------- device-global scratch (allocation-free) ----------------
__device__ __align__(16) __half g_nsrc_h[N_SRC * D];     // fp16 relu(Q h_src + b)
__device__ __align__(16) uint32_t g_nacc_h[N_DST * 64];  // fp16x2 normalized aggregate
__device__ __align__(16) uint32_t g_hdst_h[N_DST * 64];  // fp16x2 h_dst
__device__ int   g_cnt[N_DST];
__device__ int   g_startv[N_DST];
__device__ int   g_cursor[N_DST];
__device__ int   g_total;
__device__ __align__(8) uint2 g_edge[N_EDGES];           // packed (src, weight)
// fp16-packed weights (u32 = fp16x2): Q_w [128][64], W_w [128][128]
__device__ __align__(16) uint32_t g_Qh[128 * 64];
__device__ __align__(16) uint32_t g_Wh[128 * 128];

// ---------------------------------------------------------------------------
__device__ __forceinline__ void mma_f16(float* d, const uint32_t* a,
                                        const uint32_t* b) {
    asm volatile(
        "mma.sync.aligned.m16n8k16.row.col.f32.f16.f16.f32 "
        "{%0,%1,%2,%3}, {%4,%5,%6,%7}, {%8,%9}, {%0,%1,%2,%3};"
        : "+f"(d[0]), "+f"(d[1]), "+f"(d[2]), "+f"(d[3])
        : "r"(a[0]), "r"(a[1]), "r"(a[2]), "r"(a[3]),
          "r"(b[0]), "r"(b[1]));
}

__device__ __forceinline__ uint32_t f2h2(float x, float y) {
    __half2 h = __floats2half2_rn(x, y);
    return reinterpret_cast<uint32_t&>(h);
}

// ---------------------------------------------------------------------------
// Prep: zero g_cnt + g_total, pack Q_w and W_w to fp16.
// ---------------------------------------------------------------------------
__global__ void prep_kernel(const float* __restrict__ Qw,
                            const float* __restrict__ Ww) {
    const int nq = 128 * 64, nw = 128 * 128;
    int i = blockIdx.x * blockDim.x + threadIdx.x;
    if (i < N_DST) g_cnt[i] = 0;
    if (i == 0)    g_total = 0;
    if (i < nq) {
        float2 v = *(const float2*)(Qw + i * 2);
        g_Qh[i] = f2h2(v.x, v.y);
    } else if (i < nq + nw) {
        int j = i - nq;
        float2 v = *(const float2*)(Ww + j * 2);
        g_Wh[j] = f2h2(v.x, v.y);
    }
}

// Pack h_dst fp32 -> fp16x2 (stream s3, parallel with CSR chain).
__global__ void prepack_hdst_kernel(const float* __restrict__ hdst) {
    int i = blockIdx.x * blockDim.x + threadIdx.x;
    if (i >= N_DST * 64) return;
    float2 v = *(const float2*)(hdst + (size_t)i * 2);
    g_hdst_h[i] = f2h2(v.x, v.y);
}

// ---------------------------------------------------------------------------
// CSR build: histogram -> atomic segment alloc -> scatter
// ---------------------------------------------------------------------------
__global__ void hist_kernel(const int* __restrict__ edst) {
    int e = blockIdx.x * blockDim.x + threadIdx.x;
    if (e < N_EDGES) atomicAdd(&g_cnt[edst[e]], 1);
}

__global__ void alloc_kernel() {
    const int i    = blockIdx.x * blockDim.x + threadIdx.x;
    const int lane = threadIdx.x & 31;
    int c = (i < N_DST) ? g_cnt[i] : 0;
    int pfx = c;
#pragma unroll
    for (int o = 1; o < 32; o <<= 1) {
        int v = __shfl_up_sync(0xffffffffu, pfx, o);
        if (lane >= o) pfx += v;
    }
    int wtot = __shfl_sync(0xffffffffu, pfx, 31);
    int wbase = 0;
    if (lane == 31) wbase = atomicAdd(&g_total, wtot);
    wbase = __shfl_sync(0xffffffffu, wbase, 31);
    if (i < N_DST) {
        int base = wbase + pfx - c;
        g_startv[i] = base;
        g_cursor[i] = base;
    }
}

__global__ void scatter_kernel(const int* __restrict__ esrc,
                               const int* __restrict__ edst,
                               const float* __restrict__ weights) {
    int e = blockIdx.x * blockDim.x + threadIdx.x;
    if (e >= N_EDGES) return;
    int d   = edst[e];
    int pos = atomicAdd(&g_cursor[d], 1);
    g_edge[pos] = make_uint2((uint32_t)esrc[e], __float_as_uint(weights[e]));
}

// ---------------------------------------------------------------------------
// Aggregation over dst rows [base, base+count): one warp per dst, fp16 gather
// (x4 unroll), fp32 accumulate, normalized fp16 output.
// ---------------------------------------------------------------------------
__global__ void aggregate_csr_kernel(int base, int count) {
    const int idx  = (blockIdx.x * blockDim.x + threadIdx.x) >> 5;
    const int lane = threadIdx.x & 31;
    if (idx >= count) return;
    const int dst = base + idx;

    const int beg = g_startv[dst];
    const int n   = g_cnt[dst];

    float4 acc = make_float4(0.f, 0.f, 0.f, 0.f);
    float  wsum = 0.f;

#define ACC_H2(raw, ww) {                                                   \
        float2 p0 = __half22float2(*reinterpret_cast<__half2*>(&(raw).x)); \
        float2 p1 = __half22float2(*reinterpret_cast<__half2*>(&(raw).y)); \
        acc.x = fmaf(p0.x, (ww), acc.x);                                   \
        acc.y = fmaf(p0.y, (ww), acc.y);                                   \
        acc.z = fmaf(p1.x, (ww), acc.z);                                   \
        acc.w = fmaf(p1.y, (ww), acc.w); }

    int i = 0;
    for (; i + 4 <= n; i += 4) {
        uint2 e0 = g_edge[beg + i],     e1 = g_edge[beg + i + 1];
        uint2 e2 = g_edge[beg + i + 2], e3 = g_edge[beg + i + 3];
        uint2 r0 = *(const uint2*)(g_nsrc_h + (size_t)e0.x * D + lane * 4);
        uint2 r1 = *(const uint2*)(g_nsrc_h + (size_t)e1.x * D + lane * 4);
        uint2 r2 = *(const uint2*)(g_nsrc_h + (size_t)e2.x * D + lane * 4);
        uint2 r3 = *(const uint2*)(g_nsrc_h + (size_t)e3.x * D + lane * 4);
        float w0 = __uint_as_float(e0.y), w1 = __uint_as_float(e1.y);
        float w2 = __uint_as_float(e2.y), w3 = __uint_as_float(e3.y);
        ACC_H2(r0, w0); ACC_H2(r1, w1); ACC_H2(r2, w2); ACC_H2(r3, w3);
        wsum += (w0 + w1) + (w2 + w3);
    }
    for (; i < n; ++i) {
        uint2 e = g_edge[beg + i];
        float w = __uint_as_float(e.y);
        uint2 r = *(const uint2*)(g_nsrc_h + (size_t)e.x * D + lane * 4);
        ACC_H2(r, w);
        wsum += w;
    }
#undef ACC_H2

    const float inv = 1.0f / fmaxf(wsum, 1.0f);
    *(uint2*)(g_nacc_h + (size_t)dst * 64 + lane * 2) =
        make_uint2(f2h2(acc.x * inv, acc.y * inv),
                   f2h2(acc.z * inv, acc.w * inv));
}

// ---------------------------------------------------------------------------
// Unified fp16 tensor-core GEMM, 128x128 tile, BK=32, 8 warps (4m x 2n):
//   MODE 0: A = h_src fp32 (cvt in loader), B = g_Qh, KDIM=128,
//           OUT = g_nsrc_h (fp16, +bias, relu)
//   MODE 1: A = [g_nacc_h | g_hdst_h] fp16, B = g_Wh, KDIM=256,
//           OUT = d_out (fp32, +bias, relu); row_base offsets the tile grid.
// ---------------------------------------------------------------------------
template <int MODE>
__global__ void __launch_bounds__(256, 2)
gemm_f16(const float* __restrict__ A0,
         const float* __restrict__ bias,
         float* __restrict__ out,
         int row_base, int nrows)
{
    constexpr int P    = 20;
    constexpr int KDIM = (MODE == 0) ? 128 : 256;
    constexpr int BP   = (MODE == 0) ? 64 : 128;
    const uint32_t* __restrict__ Bp = (MODE == 0) ? g_Qh : g_Wh;

    __shared__ uint32_t As[128 * P];
    __shared__ uint32_t Bs[128 * P];

    const int tid    = threadIdx.x;
    const int i0     = row_base + blockIdx.x * 128;
    const int lane   = tid & 31;
    const int wid    = tid >> 5;
    const int warp_m = wid & 3;
    const int warp_n = wid >> 2;
    const int qr     = lane >> 2;
    const int qc     = lane & 3;

    float acc[2][8][4];
#pragma unroll
    for (int mt = 0; mt < 2; ++mt)
#pragma unroll
        for (int nt = 0; nt < 8; ++nt)
#pragma unroll
            for (int r = 0; r < 4; ++r) acc[mt][nt][r] = 0.f;

    const int  lrow = tid >> 1;
    const int  lkq  = (tid & 1) * 16;
    const int  gi   = i0 + lrow;
    const bool ok   = (gi < nrows);

    for (int kc = 0; kc < KDIM; kc += 32) {
        __syncthreads();
#pragma unroll
        for (int q = 0; q < 2; ++q) {
            const int gk = kc + lkq + q * 8;
            const int k2 = (lkq + q * 8) >> 1;
            uint4 a = make_uint4(0u, 0u, 0u, 0u);
            if (ok) {
                if (MODE == 0) {
                    float4 v0 = *(const float4*)(A0 + (size_t)gi * 128 + gk);
                    float4 v1 = *(const float4*)(A0 + (size_t)gi * 128 + gk + 4);
                    a = make_uint4(f2h2(v0.x, v0.y), f2h2(v0.z, v0.w),
                                   f2h2(v1.x, v1.y), f2h2(v1.z, v1.w));
                } else {
                    if (gk < 128)
                        a = *(const uint4*)(g_nacc_h + (size_t)gi * 64 + (gk >> 1));
                    else
                        a = *(const uint4*)(g_hdst_h + (size_t)gi * 64 + ((gk - 128) >> 1));
                }
            }
            *(uint4*)(As + lrow * P + k2) = a;
            *(uint4*)(Bs + lrow * P + k2) =
                *(const uint4*)(Bp + lrow * BP + (gk >> 1));
        }
        __syncthreads();

#pragma unroll
        for (int s = 0; s < 2; ++s) {
            const int ks = s * 8;
            uint32_t a[2][4];
#pragma unroll
            for (int mt = 0; mt < 2; ++mt) {
                const int base = (warp_m * 32 + mt * 16 + qr) * P + ks + qc;
                a[mt][0] = As[base];
                a[mt][1] = As[base + 8 * P];
                a[mt][2] = As[base + 4];
                a[mt][3] = As[base + 8 * P + 4];
            }
#pragma unroll
            for (int nt = 0; nt < 8; ++nt) {
                const int bb = (warp_n * 64 + nt * 8 + qr) * P + ks + qc;
                uint32_t b[2] = { Bs[bb], Bs[bb + 4] };
#pragma unroll
                for (int mt = 0; mt < 2; ++mt)
                    mma_f16(acc[mt][nt], a[mt], b);
            }
        }
    }

#pragma unroll
    for (int mt = 0; mt < 2; ++mt)
#pragma unroll
        for (int half = 0; half < 2; ++half) {
            const int row = i0 + warp_m * 32 + mt * 16 + qr + half * 8;
            if (row < nrows) {
#pragma unroll
                for (int nt = 0; nt < 8; ++nt) {
                    const int col = warp_n * 64 + nt * 8 + qc * 2;
                    float vx = fmaxf(acc[mt][nt][half * 2 + 0] + bias[col],     0.f);
                    float vy = fmaxf(acc[mt][nt][half * 2 + 1] + bias[col + 1], 0.f);
                    if (MODE == 0) {
                        *(__half2*)(g_nsrc_h + (size_t)row * 128 + col) =
                            __floats2half2_rn(vx, vy);
                    } else {
                        *(float2*)(out + (size_t)row * 128 + col) =
                            make_float2(vx, vy);
                    }
                }
            }
        }
}

// ---------------------------------------------------------------------------
// Launch graph:
//   main: prep -> gemm0 -----------------(evCSR)-> agg_h1 -> agg_h2 -> gemm1_h2 -> (evG1 join)
//   s2:        \-> hist -> alloc -> scatter -/
//   s3:        \-> hdst_pack --------(evHD)------- (evA1) -> gemm1_h1 -> evG1
// ---------------------------------------------------------------------------
extern "C" void kernel_launch(void* const* d_in, const int* in_sizes, int n_in,
                              void* d_out, int out_size)
{
    const float* h_src   = (const float*)d_in[0];
    const float* h_dst   = (const float*)d_in[1];
    const float* weights = (const float*)d_in[2];
    const int*   esrc    = (const int*)d_in[3];
    const int*   edst    = (const int*)d_in[4];
    const float* Q_w     = (const float*)d_in[5];
    const float* Q_b     = (const float*)d_in[6];
    const float* W_w     = (const float*)d_in[7];
    const float* W_b     = (const float*)d_in[8];
    float*       out     = (float*)d_out;

    static cudaStream_t s2 = nullptr, s3 = nullptr;
    static cudaEvent_t evFork = nullptr, evCSR = nullptr, evHD = nullptr,
                       evA1 = nullptr, evG1 = nullptr;
    if (!s2) {
        cudaStreamCreateWithFlags(&s2, cudaStreamNonBlocking);
        cudaStreamCreateWithFlags(&s3, cudaStreamNonBlocking);
        cudaEventCreateWithFlags(&evFork, cudaEventDisableTiming);
        cudaEventCreateWithFlags(&evCSR,  cudaEventDisableTiming);
        cudaEventCreateWithFlags(&evHD,   cudaEventDisableTiming);
        cudaEventCreateWithFlags(&evA1,   cudaEventDisableTiming);
        cudaEventCreateWithFlags(&evG1,   cudaEventDisableTiming);
    }

    prep_kernel<<<(N_DST + 255) / 256, 256>>>(Q_w, W_w);

    cudaEventRecord(evFork, 0);
    cudaStreamWaitEvent(s2, evFork, 0);
    cudaStreamWaitEvent(s3, evFork, 0);

    // s2: CSR build
    hist_kernel<<<(N_EDGES + 255) / 256, 256, 0, s2>>>(edst);
    alloc_kernel<<<(N_DST + 255) / 256, 256, 0, s2>>>();
    scatter_kernel<<<(N_EDGES + 255) / 256, 256, 0, s2>>>(esrc, edst, weights);
    cudaEventRecord(evCSR, s2);

    // s3: h_dst fp16 pack (parallel with CSR chain)
    prepack_hdst_kernel<<<(N_DST * 64 + 255) / 256, 256, 0, s3>>>(h_dst);
    cudaEventRecord(evHD, s3);

    // main: GEMM0 (overlaps s2 + s3)
    gemm_f16<0><<<(N_SRC + 127) / 128, 256>>>(h_src, Q_b, nullptr, 0, N_SRC);

    // main: aggregate half 1, then half 2
    cudaStreamWaitEvent(0, evCSR, 0);
    aggregate_csr_kernel<<<(SPLIT * 32 + 255) / 256, 256>>>(0, SPLIT);
    cudaEventRecord(evA1, 0);
    aggregate_csr_kernel<<<((N_DST - SPLIT) * 32 + 255) / 256, 256>>>(SPLIT, N_DST - SPLIT);

    // s3: gemm1 half 1 (rows [0,SPLIT)) — overlaps aggregate half 2
    cudaStreamWaitEvent(s3, evA1, 0);   // evHD already in s3 order
    gemm_f16<1><<<SPLIT / 128, 256, 0, s3>>>(nullptr, W_b, out, 0, N_DST);
    cudaEventRecord(evG1, s3);

    // main: gemm1 half 2 (rows [SPLIT,N_DST)); needs hdst pack
    cudaStreamWaitEvent(0, evHD, 0);
    gemm_f16<1><<<(N_DST - SPLIT + 127) / 128, 256>>>(nullptr, W_b, out, SPLIT, N_DST);

    // join gemm1_h1 back to the capture stream
    cudaStreamWaitEvent(0, evG1, 0);
}